// round 1
// baseline (speedup 1.0000x reference)
#include <cuda_runtime.h>
#include <math.h>

#define S_LEN  1024
#define BATCH  4
#define HEADS  16
#define DKV    64
#define DMODEL 1024
#define BHD    (BATCH * HEADS)

// ---------------- scratch (device globals; no allocation allowed) ----------------
__device__ float g_Q[BHD * S_LEN * DKV];      // [b,h][s][d]
__device__ float g_K[BHD * S_LEN * DKV];
__device__ float g_V[BHD * S_LEN * DKV];
__device__ float g_AO[BATCH * S_LEN * DMODEL]; // attn output, [b,s][h*64+d]
__device__ float g_bias[2047 * HEADS];         // rel bias per delta=j-i (+1023) per head

// ---------------- relative-position bias table ----------------
__global__ void bias_kernel(const float* __restrict__ rel_bias) {
    int t = blockIdx.x * blockDim.x + threadIdx.x;
    if (t >= 2047) return;
    int delta = t - 1023;          // j - i  (mem - ctx)
    int n = -delta;
    int ret = (n < 0) ? 16 : 0;
    n = (n < 0) ? -n : n;
    int bucket;
    if (n < 8) {
        bucket = ret + n;
    } else {
        // matches jax: log(n/8)/log(16) * 8, truncated toward zero
        float x = (logf((float)n * 0.125f) / logf(16.0f)) * 8.0f;
        int v = 8 + (int)x;
        if (v > 15) v = 15;
        bucket = ret + v;
    }
    #pragma unroll
    for (int h = 0; h < HEADS; h++)
        g_bias[t * HEADS + h] = rel_bias[bucket * HEADS + h];
}

// ---------------- generic C = A * B^T  (A:[M,K] row, B:[N,K] row) ----------------
// 128x128 tile, BK=8, 256 threads, 8x8 per thread.
// mode 0: plain row-major store to Cg[M,N]
// mode 1: QKV permuted store: m=(b,s), n=(h,d) -> Cg[((b*H+h)*S+s)*64+d]
// mode 2: batched scores (z=bh): epilogue val = acc*0.125 + bias[j-i] (+mask),
//         store to Cg + z*S*S at [i][j]
__global__ __launch_bounds__(256)
void gemm_abt_kernel(const float* __restrict__ Ag, const float* __restrict__ Bg,
                     float* __restrict__ Cg, int M, int N, int K,
                     int mode, const int* __restrict__ mask)
{
    __shared__ float As[8][128];
    __shared__ float Bs[8][128];

    int bz = blockIdx.z;
    const float* A = Ag;
    const float* B = Bg;
    if (mode == 2) {
        A += (size_t)bz * S_LEN * DKV;
        B += (size_t)bz * S_LEN * DKV;
    }
    int m0 = blockIdx.y * 128;
    int n0 = blockIdx.x * 128;
    int tid = threadIdx.x;
    int lr = tid >> 1;            // 0..127
    int lc = (tid & 1) * 4;       // 0 or 4
    int tx = tid & 15;
    int ty = tid >> 4;

    float acc[8][8];
    #pragma unroll
    for (int i = 0; i < 8; i++)
        #pragma unroll
        for (int j = 0; j < 8; j++) acc[i][j] = 0.0f;

    for (int k0 = 0; k0 < K; k0 += 8) {
        float4 a4 = *(const float4*)(A + (size_t)(m0 + lr) * K + k0 + lc);
        float4 b4 = *(const float4*)(B + (size_t)(n0 + lr) * K + k0 + lc);
        __syncthreads();
        As[lc + 0][lr] = a4.x; As[lc + 1][lr] = a4.y;
        As[lc + 2][lr] = a4.z; As[lc + 3][lr] = a4.w;
        Bs[lc + 0][lr] = b4.x; Bs[lc + 1][lr] = b4.y;
        Bs[lc + 2][lr] = b4.z; Bs[lc + 3][lr] = b4.w;
        __syncthreads();
        #pragma unroll
        for (int kk = 0; kk < 8; kk++) {
            float af[8], bf[8];
            *(float4*)(af)     = *(const float4*)(&As[kk][ty * 8]);
            *(float4*)(af + 4) = *(const float4*)(&As[kk][ty * 8 + 4]);
            *(float4*)(bf)     = *(const float4*)(&Bs[kk][tx * 8]);
            *(float4*)(bf + 4) = *(const float4*)(&Bs[kk][tx * 8 + 4]);
            #pragma unroll
            for (int i = 0; i < 8; i++)
                #pragma unroll
                for (int j = 0; j < 8; j++)
                    acc[i][j] = fmaf(af[i], bf[j], acc[i][j]);
        }
    }

    if (mode == 0) {
        #pragma unroll
        for (int i = 0; i < 8; i++) {
            int m = m0 + ty * 8 + i;
            float* crow = Cg + (size_t)m * N + n0 + tx * 8;
            *(float4*)(crow)     = make_float4(acc[i][0], acc[i][1], acc[i][2], acc[i][3]);
            *(float4*)(crow + 4) = make_float4(acc[i][4], acc[i][5], acc[i][6], acc[i][7]);
        }
    } else if (mode == 1) {
        #pragma unroll
        for (int i = 0; i < 8; i++) {
            int m = m0 + ty * 8 + i;
            int b = m >> 10, s = m & 1023;
            #pragma unroll
            for (int j = 0; j < 8; j++) {
                int n = n0 + tx * 8 + j;
                int h = n >> 6, d = n & 63;
                Cg[(((size_t)(b * HEADS + h)) * S_LEN + s) * DKV + d] = acc[i][j];
            }
        }
    } else {
        int b = bz >> 4, h = bz & 15;
        float* Cb = Cg + (size_t)bz * S_LEN * S_LEN;
        #pragma unroll
        for (int i = 0; i < 8; i++) {
            int qi = m0 + ty * 8 + i;
            #pragma unroll
            for (int j = 0; j < 8; j++) {
                int kj = n0 + tx * 8 + j;
                float v = acc[i][j] * 0.125f + g_bias[(kj - qi + 1023) * HEADS + h];
                if (mask[b * S_LEN + kj] == 0) v = -1e9f;
                Cb[(size_t)qi * S_LEN + kj] = v;
            }
        }
    }
}

// ---------------- row softmax in place over the weights buffer ----------------
__global__ __launch_bounds__(256)
void softmax_kernel(float* __restrict__ W)
{
    size_t row = blockIdx.x;
    float* p = W + row * S_LEN;
    int tid = threadIdx.x;
    float4 x = *(const float4*)(p + tid * 4);
    float m = fmaxf(fmaxf(x.x, x.y), fmaxf(x.z, x.w));
    __shared__ float red[256];
    red[tid] = m; __syncthreads();
    #pragma unroll
    for (int s = 128; s > 0; s >>= 1) {
        if (tid < s) red[tid] = fmaxf(red[tid], red[tid + s]);
        __syncthreads();
    }
    float mx = red[0];
    __syncthreads();
    float e0 = expf(x.x - mx), e1 = expf(x.y - mx);
    float e2 = expf(x.z - mx), e3 = expf(x.w - mx);
    red[tid] = (e0 + e1) + (e2 + e3); __syncthreads();
    #pragma unroll
    for (int s = 128; s > 0; s >>= 1) {
        if (tid < s) red[tid] += red[tid + s];
        __syncthreads();
    }
    float inv = 1.0f / red[0];
    *(float4*)(p + tid * 4) = make_float4(e0 * inv, e1 * inv, e2 * inv, e3 * inv);
}

// ---------------- AV: attn_out = W (row-major [S,S]) * V ([S,64]) per (b,h) ----
__global__ __launch_bounds__(256)
void av_kernel(const float* __restrict__ Wg, const float* __restrict__ Vg,
               float* __restrict__ AO)
{
    __shared__ float As[16][64];
    __shared__ float Bs[16][64];
    int bz = blockIdx.z;                 // bh
    int b = bz >> 4, h = bz & 15;
    const float* A = Wg + (size_t)bz * S_LEN * S_LEN;
    const float* V = Vg + (size_t)bz * S_LEN * DKV;
    int m0 = blockIdx.y * 64;
    int tid = threadIdx.x;
    int tx = tid & 15, ty = tid >> 4;
    int arow = tid >> 2, akc = (tid & 3) * 4;   // A: 64 rows x 16 k
    int brow = tid >> 4, bnc = (tid & 15) * 4;  // B: 16 k x 64 n

    float acc[4][4];
    #pragma unroll
    for (int i = 0; i < 4; i++)
        #pragma unroll
        for (int j = 0; j < 4; j++) acc[i][j] = 0.0f;

    for (int k0 = 0; k0 < S_LEN; k0 += 16) {
        float4 a4 = *(const float4*)(A + (size_t)(m0 + arow) * S_LEN + k0 + akc);
        float4 b4 = *(const float4*)(V + (size_t)(k0 + brow) * DKV + bnc);
        __syncthreads();
        As[akc + 0][arow] = a4.x; As[akc + 1][arow] = a4.y;
        As[akc + 2][arow] = a4.z; As[akc + 3][arow] = a4.w;
        *(float4*)(&Bs[brow][bnc]) = b4;
        __syncthreads();
        #pragma unroll
        for (int kk = 0; kk < 16; kk++) {
            float af[4], bf[4];
            *(float4*)af = *(const float4*)(&As[kk][ty * 4]);
            *(float4*)bf = *(const float4*)(&Bs[kk][tx * 4]);
            #pragma unroll
            for (int i = 0; i < 4; i++)
                #pragma unroll
                for (int j = 0; j < 4; j++)
                    acc[i][j] = fmaf(af[i], bf[j], acc[i][j]);
        }
    }
    #pragma unroll
    for (int i = 0; i < 4; i++) {
        int s = m0 + ty * 4 + i;
        float* dst = AO + ((size_t)(b * S_LEN + s)) * DMODEL + h * DKV + tx * 4;
        *(float4*)dst = make_float4(acc[i][0], acc[i][1], acc[i][2], acc[i][3]);
    }
}

// ---------------- launch ----------------
extern "C" void kernel_launch(void* const* d_in, const int* in_sizes, int n_in,
                              void* d_out, int out_size)
{
    const float* hs   = (const float*)d_in[0];
    const int*   mask = (const int*)  d_in[1];
    const float* Wq   = (const float*)d_in[2];
    const float* Wk   = (const float*)d_in[3];
    const float* Wv   = (const float*)d_in[4];
    const float* Wo   = (const float*)d_in[5];
    const float* rb   = (const float*)d_in[6];
    float* out = (float*)d_out;
    float* weights = out + (size_t)BATCH * S_LEN * DMODEL;  // attn_weights region

    float *Qp, *Kp, *Vp, *AOp;
    cudaGetSymbolAddress((void**)&Qp,  g_Q);
    cudaGetSymbolAddress((void**)&Kp,  g_K);
    cudaGetSymbolAddress((void**)&Vp,  g_V);
    cudaGetSymbolAddress((void**)&AOp, g_AO);

    // 1. bias table
    bias_kernel<<<8, 256>>>(rb);

    // 2. Q/K/V projections: [4096,1024] x [1024,1024]^T, permuted store
    dim3 gProj(DMODEL / 128, (BATCH * S_LEN) / 128, 1);
    gemm_abt_kernel<<<gProj, 256>>>(hs, Wq, Qp, BATCH * S_LEN, DMODEL, DMODEL, 1, nullptr);
    gemm_abt_kernel<<<gProj, 256>>>(hs, Wk, Kp, BATCH * S_LEN, DMODEL, DMODEL, 1, nullptr);
    gemm_abt_kernel<<<gProj, 256>>>(hs, Wv, Vp, BATCH * S_LEN, DMODEL, DMODEL, 1, nullptr);

    // 3. scores = QK^T/8 + bias (+mask), batched over bh -> raw scores in weights buf
    dim3 gScore(S_LEN / 128, S_LEN / 128, BHD);
    gemm_abt_kernel<<<gScore, 256>>>(Qp, Kp, weights, S_LEN, S_LEN, DKV, 2, mask);

    // 4. softmax in place (one block per row)
    softmax_kernel<<<BHD * S_LEN, 256>>>(weights);

    // 5. attn @ V -> g_AO
    dim3 gAV(1, S_LEN / 64, BHD);
    av_kernel<<<gAV, 256>>>(weights, Vp, AOp);

    // 6. output projection -> d_out[0 : B*S*D]
    gemm_abt_kernel<<<gProj, 256>>>(AOp, Wo, out, BATCH * S_LEN, DMODEL, DMODEL, 0, nullptr);
}

// round 3
// speedup vs baseline: 1.6813x; 1.6813x over previous
#include <cuda_runtime.h>
#include <cuda_bf16.h>
#include <math.h>
#include <stdint.h>

#define S_LEN  1024
#define BATCH  4
#define HEADS  16
#define DKV    64
#define DMODEL 1024
#define BHD    (BATCH * HEADS)

// ---------------- scratch (device globals; no allocation allowed) ----------------
__device__ float g_Q[BHD * S_LEN * DKV];       // [b,h][s][d]
__device__ float g_K[BHD * S_LEN * DKV];       // [b,h][s][d]
__device__ float g_V[BHD * S_LEN * DKV];       // TRANSPOSED: [b,h][d][s]
__device__ float g_AO[BATCH * S_LEN * DMODEL]; // attn output, [b,s][h*64+d]
__device__ float g_bias[2047 * HEADS];         // rel bias per delta=j-i (+1023) per head

// ================= helpers =================
#define SWZ(o) ((o) ^ ((((o) >> 3)) & 0x70))

static __device__ __forceinline__ uint32_t smem_u32(const void* p) {
    uint32_t a;
    asm("{ .reg .u64 t; cvta.to.shared.u64 t, %1; cvt.u32.u64 %0, t; }" : "=r"(a) : "l"(p));
    return a;
}

static __device__ __forceinline__ void ldsm4(uint32_t* r, uint32_t addr) {
    asm volatile("ldmatrix.sync.aligned.m8n8.x4.shared.b16 {%0,%1,%2,%3}, [%4];"
                 : "=r"(r[0]), "=r"(r[1]), "=r"(r[2]), "=r"(r[3]) : "r"(addr));
}

static __device__ __forceinline__ void hmma(float* c, const uint32_t* a, const uint32_t* b) {
    asm volatile(
        "mma.sync.aligned.m16n8k16.row.col.f32.bf16.bf16.f32 "
        "{%0,%1,%2,%3}, {%4,%5,%6,%7}, {%8,%9}, {%0,%1,%2,%3};"
        : "+f"(c[0]), "+f"(c[1]), "+f"(c[2]), "+f"(c[3])
        : "r"(a[0]), "r"(a[1]), "r"(a[2]), "r"(a[3]), "r"(b[0]), "r"(b[1]));
}

// split fp32 -> bf16 hi + bf16 lo (residual), store 8 elems (16B hi + 16B lo)
static __device__ __forceinline__ void cvt_store8(char* ph, char* pl, float4 f0, float4 f1) {
    float v[8] = {f0.x, f0.y, f0.z, f0.w, f1.x, f1.y, f1.z, f1.w};
    uint32_t h[4], l[4];
    #pragma unroll
    for (int i = 0; i < 4; i++) {
        __nv_bfloat16 a = __float2bfloat16(v[2 * i]);
        __nv_bfloat16 b = __float2bfloat16(v[2 * i + 1]);
        float ra = v[2 * i] - __bfloat162float(a);
        float rb = v[2 * i + 1] - __bfloat162float(b);
        __nv_bfloat16 la = __float2bfloat16(ra);
        __nv_bfloat16 lb = __float2bfloat16(rb);
        h[i] = (uint32_t)__bfloat16_as_ushort(a) | ((uint32_t)__bfloat16_as_ushort(b) << 16);
        l[i] = (uint32_t)__bfloat16_as_ushort(la) | ((uint32_t)__bfloat16_as_ushort(lb) << 16);
    }
    *(uint4*)ph = make_uint4(h[0], h[1], h[2], h[3]);
    *(uint4*)pl = make_uint4(l[0], l[1], l[2], l[3]);
}

// ================= bias table =================
__global__ void bias_kernel(const float* __restrict__ rel_bias) {
    int t = blockIdx.x * blockDim.x + threadIdx.x;
    if (t >= 2047) return;
    int delta = t - 1023;
    int n = -delta;
    int ret = (n < 0) ? 16 : 0;
    n = (n < 0) ? -n : n;
    int bucket;
    if (n < 8) {
        bucket = ret + n;
    } else {
        float x = (logf((float)n * 0.125f) / logf(16.0f)) * 8.0f;
        int v = 8 + (int)x;
        if (v > 15) v = 15;
        bucket = ret + v;
    }
    #pragma unroll
    for (int h = 0; h < HEADS; h++)
        g_bias[t * HEADS + h] = rel_bias[bucket * HEADS + h];
}

// ================= mma.sync bf16-split GEMM: C = A * B^T ======================
// CTA tile: M=128, N=64, K-chunk=64. 256 threads (8 warps, 4m x 2n), warp 32x32.
// MODE 0: plain store C0[m][1024], K=1024   (output projection)
// MODE 1: fused QKV, z: 0->Q,1->K (per-head [s][d]); 2->V transposed [d][s]. K=1024
// MODE 2: scores per z=bh: acc*0.125 + bias + mask -> C0 + z*S*S. K=64
// MODE 3: AV per z=bh: A=weights [S][S], B=Vt (rows=d, ld=S). K=1024 -> AO

#define STAGE_BYTES 49152   // A_hi 16K | A_lo 16K | B_hi 8K | B_lo 8K
#define SMEM_TOTAL  (2 * STAGE_BYTES)

struct StageA { float4 r[8]; };
struct StageB { float4 r[4]; };

template <int MODE>
__global__ __launch_bounds__(256)
void mma_gemm(const float* __restrict__ A,
              const float* __restrict__ B0, const float* __restrict__ B1,
              const float* __restrict__ B2,
              float* __restrict__ C0, float* __restrict__ C1, float* __restrict__ C2,
              const int* __restrict__ mask)
{
    constexpr int K   = (MODE == 2) ? 64 : 1024;
    constexpr int LD  = (MODE == 2) ? 64 : 1024;   // both A and B leading dims
    constexpr int NC  = K / 64;

    extern __shared__ char smem[];
    const uint32_t sb = smem_u32(smem);
    const int tid = threadIdx.x;
    const int lane = tid & 31, wid = tid >> 5;
    const int wm = wid >> 1, wn = wid & 1;
    const int z  = blockIdx.z;
    const int m0 = blockIdx.y * 128;
    const int n0 = blockIdx.x * 64;

    const float* Ap = A;
    const float* Bp = B0;
    if (MODE == 1) Bp = (z == 0) ? B0 : ((z == 1) ? B1 : B2);
    if (MODE == 2) { Ap = A + (size_t)z * S_LEN * DKV;  Bp = B0 + (size_t)z * S_LEN * DKV; }
    if (MODE == 3) { Ap = A + (size_t)z * S_LEN * S_LEN; Bp = B0 + (size_t)z * S_LEN * DKV; }

    // per-thread fill indices
    const int ar = tid >> 1, ah_ = tid & 1;      // A: row, 32-col half
    const int br = tid >> 2, bq = tid & 3;       // B: row, 16-col quarter

    // per-thread ldmatrix base offsets (byte offsets into a tile, pre-swizzle row part)
    const int a_row = (wm * 32 + (lane & 15));
    const int a_colb = (lane >> 4) * 16;
    const int b_row = (wn * 32 + ((lane >> 4) & 1) * 8 + (lane & 7));
    const int b_colb = ((lane >> 3) & 1) * 16;

    float c[2][4][4];
    #pragma unroll
    for (int i = 0; i < 2; i++)
        #pragma unroll
        for (int j = 0; j < 4; j++)
            #pragma unroll
            for (int u = 0; u < 4; u++) c[i][j][u] = 0.0f;

    StageA ra; StageB rb;

    auto load_stage = [&](int cc) {
        const float* As = Ap + (size_t)(m0 + ar) * LD + cc * 64 + ah_ * 32;
        #pragma unroll
        for (int j = 0; j < 8; j++) ra.r[j] = *(const float4*)(As + j * 4);
        const float* Bs = Bp + (size_t)(n0 + br) * LD + cc * 64 + bq * 16;
        #pragma unroll
        for (int j = 0; j < 4; j++) rb.r[j] = *(const float4*)(Bs + j * 4);
    };

    auto store_stage = [&](int st) {
        char* base = smem + st * STAGE_BYTES;
        char* aH = base;          char* aL = base + 16384;
        char* bH = base + 32768;  char* bL = base + 40960;
        #pragma unroll
        for (int j = 0; j < 4; j++) {
            uint32_t sw = SWZ((uint32_t)(ar * 128 + ah_ * 64 + j * 16));
            cvt_store8(aH + sw, aL + sw, ra.r[2 * j], ra.r[2 * j + 1]);
        }
        #pragma unroll
        for (int j = 0; j < 2; j++) {
            uint32_t sw = SWZ((uint32_t)(br * 128 + bq * 32 + j * 16));
            cvt_store8(bH + sw, bL + sw, rb.r[2 * j], rb.r[2 * j + 1]);
        }
    };

    auto compute = [&](int st) {
        const uint32_t base = sb + st * STAGE_BYTES;
        const uint32_t aH = base, aL = base + 16384;
        const uint32_t bH = base + 32768, bL = base + 40960;
        #pragma unroll
        for (int ks = 0; ks < 4; ks++) {
            uint32_t fah[2][4], fal[2][4], fbh[2][4], fbl[2][4];
            #pragma unroll
            for (int mt = 0; mt < 2; mt++) {
                uint32_t off = SWZ((uint32_t)((a_row + mt * 16) * 128 + ks * 32 + a_colb));
                ldsm4(fah[mt], aH + off);
                ldsm4(fal[mt], aL + off);
            }
            #pragma unroll
            for (int nt2 = 0; nt2 < 2; nt2++) {
                uint32_t off = SWZ((uint32_t)((b_row + nt2 * 16) * 128 + ks * 32 + b_colb));
                ldsm4(fbh[nt2], bH + off);
                ldsm4(fbl[nt2], bL + off);
            }
            #pragma unroll
            for (int mt = 0; mt < 2; mt++)
                #pragma unroll
                for (int nt = 0; nt < 4; nt++) {
                    const uint32_t* ph = &fbh[nt >> 1][(nt & 1) * 2];
                    const uint32_t* pl = &fbl[nt >> 1][(nt & 1) * 2];
                    hmma(c[mt][nt], fah[mt], ph);
                    hmma(c[mt][nt], fah[mt], pl);
                    hmma(c[mt][nt], fal[mt], ph);
                }
        }
    };

    // software-pipelined mainloop
    load_stage(0);
    store_stage(0);
    __syncthreads();
    #pragma unroll 1
    for (int cc = 1; cc < NC; cc++) {
        load_stage(cc);
        compute((cc - 1) & 1);
        __syncthreads();
        store_stage(cc & 1);
        __syncthreads();
    }
    compute((NC - 1) & 1);

    // ---------------- epilogue ----------------
    const int mrow = (lane >> 2);
    const int ncol = 2 * (lane & 3);
    #pragma unroll
    for (int mt = 0; mt < 2; mt++) {
        #pragma unroll
        for (int nt = 0; nt < 4; nt++) {
            int mg = m0 + wm * 32 + mt * 16 + mrow;
            int ng = n0 + wn * 32 + nt * 8 + ncol;
            float* cf = c[mt][nt];
            if (MODE == 0) {
                *(float2*)(C0 + (size_t)mg * DMODEL + ng)       = make_float2(cf[0], cf[1]);
                *(float2*)(C0 + (size_t)(mg + 8) * DMODEL + ng) = make_float2(cf[2], cf[3]);
            } else if (MODE == 1) {
                int h = blockIdx.x;                 // n block == head (BN=64)
                int d = ng & 63;
                if (z < 2) {
                    float* Cd = (z == 0) ? C0 : C1;
                    int b = mg >> 10, s = mg & 1023;
                    float* r0 = Cd + (((size_t)(b * HEADS + h)) * S_LEN + s) * DKV + d;
                    *(float2*)r0 = make_float2(cf[0], cf[1]);
                    float* r1 = Cd + (((size_t)(b * HEADS + h)) * S_LEN + (s + 8)) * DKV + d;
                    *(float2*)r1 = make_float2(cf[2], cf[3]);
                } else {
                    int b = mg >> 10, s = mg & 1023;
                    size_t bh = (size_t)(b * HEADS + h);
                    C2[(bh * DKV + d)     * S_LEN + s]     = cf[0];
                    C2[(bh * DKV + d + 1) * S_LEN + s]     = cf[1];
                    C2[(bh * DKV + d)     * S_LEN + s + 8] = cf[2];
                    C2[(bh * DKV + d + 1) * S_LEN + s + 8] = cf[3];
                }
            } else if (MODE == 2) {
                int b = z >> 4, h = z & 15;
                float* Cb = C0 + (size_t)z * S_LEN * S_LEN;
                int qi0 = mg, qi1 = mg + 8;
                float v0 = cf[0] * 0.125f + g_bias[(ng     - qi0 + 1023) * HEADS + h];
                float v1 = cf[1] * 0.125f + g_bias[(ng + 1 - qi0 + 1023) * HEADS + h];
                float v2 = cf[2] * 0.125f + g_bias[(ng     - qi1 + 1023) * HEADS + h];
                float v3 = cf[3] * 0.125f + g_bias[(ng + 1 - qi1 + 1023) * HEADS + h];
                if (mask[b * S_LEN + ng] == 0)     { v0 = -1e9f; v2 = -1e9f; }
                if (mask[b * S_LEN + ng + 1] == 0) { v1 = -1e9f; v3 = -1e9f; }
                *(float2*)(Cb + (size_t)qi0 * S_LEN + ng) = make_float2(v0, v1);
                *(float2*)(Cb + (size_t)qi1 * S_LEN + ng) = make_float2(v2, v3);
            } else { // MODE 3
                int b = z >> 4, h = z & 15;
                float* r0 = C0 + ((size_t)(b * S_LEN + mg)) * DMODEL + h * DKV + ng;
                *(float2*)r0 = make_float2(cf[0], cf[1]);
                float* r1 = C0 + ((size_t)(b * S_LEN + mg + 8)) * DMODEL + h * DKV + ng;
                *(float2*)r1 = make_float2(cf[2], cf[3]);
            }
        }
    }
}

// ================= row softmax in place =================
__global__ __launch_bounds__(256)
void softmax_kernel(float* __restrict__ W)
{
    size_t row = blockIdx.x;
    float* p = W + row * S_LEN;
    int tid = threadIdx.x;
    float4 x = *(const float4*)(p + tid * 4);
    float m = fmaxf(fmaxf(x.x, x.y), fmaxf(x.z, x.w));
    __shared__ float red[256];
    red[tid] = m; __syncthreads();
    #pragma unroll
    for (int s = 128; s > 0; s >>= 1) {
        if (tid < s) red[tid] = fmaxf(red[tid], red[tid + s]);
        __syncthreads();
    }
    float mx = red[0];
    __syncthreads();
    float e0 = expf(x.x - mx), e1 = expf(x.y - mx);
    float e2 = expf(x.z - mx), e3 = expf(x.w - mx);
    red[tid] = (e0 + e1) + (e2 + e3); __syncthreads();
    #pragma unroll
    for (int s = 128; s > 0; s >>= 1) {
        if (tid < s) red[tid] += red[tid + s];
        __syncthreads();
    }
    float inv = 1.0f / red[0];
    *(float4*)(p + tid * 4) = make_float4(e0 * inv, e1 * inv, e2 * inv, e3 * inv);
}

// ================= launch =================
extern "C" void kernel_launch(void* const* d_in, const int* in_sizes, int n_in,
                              void* d_out, int out_size)
{
    const float* hs   = (const float*)d_in[0];
    const int*   mask = (const int*)  d_in[1];
    const float* Wq   = (const float*)d_in[2];
    const float* Wk   = (const float*)d_in[3];
    const float* Wv   = (const float*)d_in[4];
    const float* Wo   = (const float*)d_in[5];
    const float* rb   = (const float*)d_in[6];
    float* out = (float*)d_out;
    float* weights = out + (size_t)BATCH * S_LEN * DMODEL;

    float *Qp, *Kp, *Vp, *AOp;
    cudaGetSymbolAddress((void**)&Qp,  g_Q);
    cudaGetSymbolAddress((void**)&Kp,  g_K);
    cudaGetSymbolAddress((void**)&Vp,  g_V);
    cudaGetSymbolAddress((void**)&AOp, g_AO);

    cudaFuncSetAttribute(mma_gemm<0>, cudaFuncAttributeMaxDynamicSharedMemorySize, SMEM_TOTAL);
    cudaFuncSetAttribute(mma_gemm<1>, cudaFuncAttributeMaxDynamicSharedMemorySize, SMEM_TOTAL);
    cudaFuncSetAttribute(mma_gemm<2>, cudaFuncAttributeMaxDynamicSharedMemorySize, SMEM_TOTAL);
    cudaFuncSetAttribute(mma_gemm<3>, cudaFuncAttributeMaxDynamicSharedMemorySize, SMEM_TOTAL);

    // 1. bias table
    bias_kernel<<<8, 256>>>(rb);

    // 2. fused Q/K/V projections (z selects weight + dst; V stored transposed)
    mma_gemm<1><<<dim3(DMODEL / 64, (BATCH * S_LEN) / 128, 3), 256, SMEM_TOTAL>>>(
        hs, Wq, Wk, Wv, Qp, Kp, Vp, nullptr);

    // 3. scores = QK^T/8 + bias (+mask) -> weights buffer
    mma_gemm<2><<<dim3(S_LEN / 64, S_LEN / 128, BHD), 256, SMEM_TOTAL>>>(
        Qp, Kp, nullptr, nullptr, weights, nullptr, nullptr, mask);

    // 4. softmax in place
    softmax_kernel<<<BHD * S_LEN, 256>>>(weights);

    // 5. attn @ V -> g_AO
    mma_gemm<3><<<dim3(1, S_LEN / 128, BHD), 256, SMEM_TOTAL>>>(
        weights, Vp, nullptr, nullptr, AOp, nullptr, nullptr, nullptr);

    // 6. output projection
    mma_gemm<0><<<dim3(DMODEL / 64, (BATCH * S_LEN) / 128, 1), 256, SMEM_TOTAL>>>(
        AOp, Wo, nullptr, nullptr, out, nullptr, nullptr, nullptr);
}

// round 4
// speedup vs baseline: 1.7302x; 1.0291x over previous
#include <cuda_runtime.h>
#include <cuda_bf16.h>
#include <math.h>
#include <stdint.h>

#define S_LEN  1024
#define BATCH  4
#define HEADS  16
#define DKV    64
#define DMODEL 1024
#define BHD    (BATCH * HEADS)

typedef __nv_bfloat16 bf16;

// ---------------- scratch (device globals; no allocation allowed) ----------------
__device__ bf16 g_hsH[4096 * 1024];
__device__ bf16 g_hsL[4096 * 1024];
__device__ bf16 g_WH[4 * 1024 * 1024];     // q,k,v,o
__device__ bf16 g_WL[4 * 1024 * 1024];
__device__ bf16 g_QKVH[3 * BHD * 1024 * 64]; // z: 0 Q, 1 K, 2 V; [bh][s][64]
__device__ bf16 g_QKVL[3 * BHD * 1024 * 64];
__device__ bf16 g_AOH[4096 * 1024];
__device__ bf16 g_AOL[4096 * 1024];
__device__ float g_bias2[16 * 2048];       // [h][delta+1023]

// ================= helpers =================
#define SWZ(o) ((o) ^ ((((o) >> 3)) & 0x70))

static __device__ __forceinline__ uint32_t smem_u32(const void* p) {
    uint32_t a;
    asm("{ .reg .u64 t; cvta.to.shared.u64 t, %1; cvt.u32.u64 %0, t; }" : "=r"(a) : "l"(p));
    return a;
}

static __device__ __forceinline__ void ldsm4(uint32_t* r, uint32_t addr) {
    asm volatile("ldmatrix.sync.aligned.m8n8.x4.shared.b16 {%0,%1,%2,%3}, [%4];"
                 : "=r"(r[0]), "=r"(r[1]), "=r"(r[2]), "=r"(r[3]) : "r"(addr));
}

static __device__ __forceinline__ void hmma(float* c, const uint32_t* a, const uint32_t* b) {
    asm volatile(
        "mma.sync.aligned.m16n8k16.row.col.f32.bf16.bf16.f32 "
        "{%0,%1,%2,%3}, {%4,%5,%6,%7}, {%8,%9}, {%0,%1,%2,%3};"
        : "+f"(c[0]), "+f"(c[1]), "+f"(c[2]), "+f"(c[3])
        : "r"(a[0]), "r"(a[1]), "r"(a[2]), "r"(a[3]), "r"(b[0]), "r"(b[1]));
}

#define CP_ASYNC16(dst, src) \
    asm volatile("cp.async.ca.shared.global [%0], [%1], 16;" :: "r"(dst), "l"(src))
#define CP_COMMIT() asm volatile("cp.async.commit_group;" ::: "memory")
#define CP_WAIT(n)  asm volatile("cp.async.wait_group %0;" :: "n"(n) : "memory")

static __device__ __forceinline__ uint32_t pack_hi(float a, float b) {
    __nv_bfloat16 x = __float2bfloat16(a), y = __float2bfloat16(b);
    return (uint32_t)__bfloat16_as_ushort(x) | ((uint32_t)__bfloat16_as_ushort(y) << 16);
}
static __device__ __forceinline__ uint32_t pack_lo(float a, float b) {
    __nv_bfloat16 x = __float2bfloat16(a), y = __float2bfloat16(b);
    float ra = a - __bfloat162float(x), rb = b - __bfloat162float(y);
    __nv_bfloat16 lx = __float2bfloat16(ra), ly = __float2bfloat16(rb);
    return (uint32_t)__bfloat16_as_ushort(lx) | ((uint32_t)__bfloat16_as_ushort(ly) << 16);
}

// ================= split fp32 -> bf16 hi/lo =================
__global__ __launch_bounds__(256)
void split_kernel(const float* __restrict__ in, bf16* __restrict__ hi,
                  bf16* __restrict__ lo, int n4)
{
    int t = blockIdx.x * blockDim.x + threadIdx.x;
    if (t >= n4) return;
    float4 v = ((const float4*)in)[t];
    uint2 h, l;
    h.x = pack_hi(v.x, v.y); h.y = pack_hi(v.z, v.w);
    l.x = pack_lo(v.x, v.y); l.y = pack_lo(v.z, v.w);
    ((uint2*)hi)[t] = h;
    ((uint2*)lo)[t] = l;
}

// ================= bias table: g_bias2[h][delta+1023] =================
__global__ void bias_kernel(const float* __restrict__ rel_bias) {
    int t = blockIdx.x * blockDim.x + threadIdx.x;
    if (t >= 2048) return;
    int delta = t - 1023;
    int n = -delta;
    int ret = (n < 0) ? 16 : 0;
    n = (n < 0) ? -n : n;
    int bucket;
    if (n < 8) {
        bucket = ret + n;
    } else {
        float x = (logf((float)n * 0.125f) / logf(16.0f)) * 8.0f;
        int v = 8 + (int)x;
        if (v > 15) v = 15;
        bucket = ret + v;
    }
    #pragma unroll
    for (int h = 0; h < HEADS; h++)
        g_bias2[h * 2048 + t] = rel_bias[bucket * HEADS + h];
}

// ================= proj GEMM (bf16 split, cp.async, 128x128 tile) =============
// C = A * B^T, A [M][1024] hi/lo bf16, B [1024][1024] hi/lo bf16, K = 1024.
// EPI 0: store fp32 C [M][1024]
// EPI 1: QKV: z = blockIdx.z selects W slice + dst slice; store bf16 hi/lo
//         at [bh][s][64] with h = n>>6.
#define PSTAGE 65536          // A hi 16K | A lo 16K | B hi 16K | B lo 16K
#define PSMEM  (2 * PSTAGE)

template <int EPI>
__global__ __launch_bounds__(256)
void proj_gemm(const bf16* __restrict__ AH, const bf16* __restrict__ AL,
               const bf16* __restrict__ BH, const bf16* __restrict__ BL,
               float* __restrict__ Cf, bf16* __restrict__ CH, bf16* __restrict__ CL)
{
    extern __shared__ char smem[];
    const uint32_t sb = smem_u32(smem);
    const int tid = threadIdx.x;
    const int lane = tid & 31, wid = tid >> 5;
    const int wm = wid >> 1, wn = wid & 1;
    const int m0 = blockIdx.y * 128;
    const int n0 = blockIdx.x * 128;
    const int z = blockIdx.z;

    const bf16* BHp = BH;
    const bf16* BLp = BL;
    bf16* CHp = CH;
    bf16* CLp = CL;
    if (EPI == 1) {
        BHp += (size_t)z * 1048576; BLp += (size_t)z * 1048576;
        CHp += (size_t)z * 4194304; CLp += (size_t)z * 4194304;
    }

    float c[2][8][4];
    #pragma unroll
    for (int i = 0; i < 2; i++)
        #pragma unroll
        for (int j = 0; j < 8; j++)
            #pragma unroll
            for (int u = 0; u < 4; u++) c[i][j][u] = 0.0f;

    auto fill = [&](int st, int k0) {
        uint32_t base = sb + st * PSTAGE;
        #pragma unroll
        for (int arr = 0; arr < 4; arr++) {
            const bf16* sp = (arr == 0) ? AH : (arr == 1) ? AL : (arr == 2) ? BHp : BLp;
            int rbase = (arr < 2) ? m0 : n0;
            #pragma unroll
            for (int j = 0; j < 4; j++) {
                int idx = j * 256 + tid;
                int row = idx >> 3, c16 = idx & 7;
                const void* src = sp + (size_t)(rbase + row) * 1024 + k0 + c16 * 8;
                uint32_t dst = base + arr * 16384 + SWZ(row * 128 + c16 * 16);
                CP_ASYNC16(dst, src);
            }
        }
        CP_COMMIT();
    };

    const int a_row = wm * 32 + (lane & 15);
    const int a_colb = (lane >> 4) * 16;
    const int b_rowb = wn * 64 + ((lane >> 4) & 1) * 8 + (lane & 7);
    const int b_colb = ((lane >> 3) & 1) * 16;

    auto compute = [&](int st) {
        const uint32_t base = sb + st * PSTAGE;
        const uint32_t aH = base, aL = base + 16384;
        const uint32_t bH = base + 32768, bL = base + 49152;
        #pragma unroll
        for (int ks = 0; ks < 4; ks++) {
            uint32_t fah[2][4], fal[2][4];
            #pragma unroll
            for (int mt = 0; mt < 2; mt++) {
                uint32_t off = SWZ((uint32_t)((a_row + mt * 16) * 128 + ks * 32 + a_colb));
                ldsm4(fah[mt], aH + off);
                ldsm4(fal[mt], aL + off);
            }
            #pragma unroll
            for (int nt2 = 0; nt2 < 4; nt2++) {
                uint32_t off = SWZ((uint32_t)((b_rowb + nt2 * 16) * 128 + ks * 32 + b_colb));
                uint32_t fbh[4], fbl[4];
                ldsm4(fbh, bH + off);
                ldsm4(fbl, bL + off);
                #pragma unroll
                for (int mt = 0; mt < 2; mt++)
                    #pragma unroll
                    for (int half = 0; half < 2; half++) {
                        int nt = nt2 * 2 + half;
                        hmma(c[mt][nt], fah[mt], &fbh[half * 2]);
                        hmma(c[mt][nt], fah[mt], &fbl[half * 2]);
                        hmma(c[mt][nt], fal[mt], &fbh[half * 2]);
                    }
            }
        }
    };

    fill(0, 0);
    #pragma unroll 1
    for (int cc = 0; cc < 16; cc++) {
        if (cc + 1 < 16) { fill((cc + 1) & 1, (cc + 1) * 64); CP_WAIT(1); }
        else             { CP_WAIT(0); }
        __syncthreads();
        compute(cc & 1);
        __syncthreads();
    }

    // epilogue
    #pragma unroll
    for (int mt = 0; mt < 2; mt++)
        #pragma unroll
        for (int nt = 0; nt < 8; nt++) {
            int mg = m0 + wm * 32 + mt * 16 + (lane >> 2);
            int ng = n0 + wn * 64 + nt * 8 + 2 * (lane & 3);
            float* cf = c[mt][nt];
            if (EPI == 0) {
                *(float2*)(Cf + (size_t)mg * 1024 + ng)       = make_float2(cf[0], cf[1]);
                *(float2*)(Cf + (size_t)(mg + 8) * 1024 + ng) = make_float2(cf[2], cf[3]);
            } else {
                int h = ng >> 6, d = ng & 63;
                int b = mg >> 10, s = mg & 1023;
                size_t i0 = ((size_t)(b * HEADS + h) * 1024 + s) * 64 + d;
                size_t i1 = ((size_t)(b * HEADS + h) * 1024 + s + 8) * 64 + d;
                *(uint32_t*)(CHp + i0) = pack_hi(cf[0], cf[1]);
                *(uint32_t*)(CLp + i0) = pack_lo(cf[0], cf[1]);
                *(uint32_t*)(CHp + i1) = pack_hi(cf[2], cf[3]);
                *(uint32_t*)(CLp + i1) = pack_lo(cf[2], cf[3]);
            }
        }
}

// ================= fused attention: scores + bias + mask + softmax + AV =======
// grid (32 qtiles, 64 bh), 256 threads. smem:
#define OFF_SC   0          // 32x1024 fp32 scores/P      (131072)
#define OFF_QH   131072     // Q hi  32x64 bf16           (4096)
#define OFF_QL   135168
#define OFF_KH   139264     // K chunk 128x64 bf16 (also Vt 64x64)  (16384)
#define OFF_KL   155648
#define OFF_PH   172032     // P chunk 32x64 bf16         (4096)
#define OFF_PL   176128
#define OFF_BIAS 180224     // 1056 floats                (4224->4352 pad)
#define OFF_MASK 184576     // 1024 ints                  (4096)
#define ASMEM    188672

__global__ __launch_bounds__(256)
void attn_fused(const int* __restrict__ mask, float* __restrict__ weights,
                const bf16* __restrict__ QKVH, const bf16* __restrict__ QKVL,
                bf16* __restrict__ AOH, bf16* __restrict__ AOL)
{
    extern __shared__ char smem[];
    const uint32_t sb = smem_u32(smem);
    const int tid = threadIdx.x;
    const int lane = tid & 31, wid = tid >> 5;
    const int bh = blockIdx.y;
    const int b = bh >> 4, h = bh & 15;
    const int q0 = blockIdx.x * 32;

    // --- Q tile fill (32x64 hi/lo) ---
    {
        int row = tid >> 3, seg = tid & 7;
        const uint4* srcH = (const uint4*)(QKVH + ((size_t)bh * 1024 + q0 + row) * 64 + seg * 8);
        const uint4* srcL = (const uint4*)(QKVL + ((size_t)bh * 1024 + q0 + row) * 64 + seg * 8);
        uint32_t sw = SWZ((uint32_t)(row * 128 + seg * 16));
        *(uint4*)(smem + OFF_QH + sw) = *srcH;
        *(uint4*)(smem + OFF_QL + sw) = *srcL;
    }
    // --- bias slice: bias_sm[x] = g_bias2[h*2048 + x + 992 - q0], x in [0,1056) ---
    for (int i = tid; i < 1056; i += 256)
        *(float*)(smem + OFF_BIAS + i * 4) = g_bias2[h * 2048 + i + 992 - q0];
    // --- mask row ---
    for (int i = tid; i < 1024; i += 256)
        *(int*)(smem + OFF_MASK + i * 4) = mask[b * 1024 + i];
    __syncthreads();

    // ======== scores phase: 8 chunks of 128 j-columns ========
    const int a_row = (lane & 15);
    const int a_colb = (lane >> 4) * 16;
    const int wn = wid;                        // n-slice of 16 per warp
    const int b_rowb = wn * 16 + ((lane >> 4) & 1) * 8 + (lane & 7);
    const int b_colb = ((lane >> 3) & 1) * 16;

    #pragma unroll 1
    for (int jc = 0; jc < 8; jc++) {
        const int j0 = jc * 128;
        // fill K chunk [128][64] hi/lo
        #pragma unroll
        for (int it = 0; it < 8; it++) {
            int g = it * 256 + tid;
            int arr = g >> 10, rem = g & 1023;
            int row = rem >> 3, seg = rem & 7;
            const bf16* sp = arr ? QKVL : QKVH;
            const uint4* src = (const uint4*)(sp + ((size_t)(BHD + bh) * 1024 + j0 + row) * 64 + seg * 8);
            uint32_t dst = (arr ? OFF_KL : OFF_KH) + SWZ((uint32_t)(row * 128 + seg * 16));
            *(uint4*)(smem + dst) = *src;
        }
        __syncthreads();

        float c2[2][2][4];
        #pragma unroll
        for (int i = 0; i < 2; i++)
            #pragma unroll
            for (int j = 0; j < 2; j++)
                #pragma unroll
                for (int u = 0; u < 4; u++) c2[i][j][u] = 0.0f;

        #pragma unroll
        for (int ks = 0; ks < 4; ks++) {
            uint32_t fah[2][4], fal[2][4];
            #pragma unroll
            for (int mt = 0; mt < 2; mt++) {
                uint32_t off = SWZ((uint32_t)((a_row + mt * 16) * 128 + ks * 32 + a_colb));
                ldsm4(fah[mt], sb + OFF_QH + off);
                ldsm4(fal[mt], sb + OFF_QL + off);
            }
            uint32_t off = SWZ((uint32_t)(b_rowb * 128 + ks * 32 + b_colb));
            uint32_t fbh[4], fbl[4];
            ldsm4(fbh, sb + OFF_KH + off);
            ldsm4(fbl, sb + OFF_KL + off);
            #pragma unroll
            for (int mt = 0; mt < 2; mt++)
                #pragma unroll
                for (int nt = 0; nt < 2; nt++) {
                    hmma(c2[mt][nt], fah[mt], &fbh[nt * 2]);
                    hmma(c2[mt][nt], fah[mt], &fbl[nt * 2]);
                    hmma(c2[mt][nt], fal[mt], &fbh[nt * 2]);
                }
        }

        // epilogue -> smem scores with bias + mask
        #pragma unroll
        for (int mt = 0; mt < 2; mt++)
            #pragma unroll
            for (int nt = 0; nt < 2; nt++) {
                int ml0 = mt * 16 + (lane >> 2);
                int jg = j0 + wn * 16 + nt * 8 + 2 * (lane & 3);
                float* cf = c2[mt][nt];
                int mk0 = *(int*)(smem + OFF_MASK + jg * 4);
                int mk1 = *(int*)(smem + OFF_MASK + (jg + 1) * 4);
                float v0 = cf[0] * 0.125f + *(float*)(smem + OFF_BIAS + (jg - ml0 + 31) * 4);
                float v1 = cf[1] * 0.125f + *(float*)(smem + OFF_BIAS + (jg + 1 - ml0 + 31) * 4);
                int ml1 = ml0 + 8;
                float v2 = cf[2] * 0.125f + *(float*)(smem + OFF_BIAS + (jg - ml1 + 31) * 4);
                float v3 = cf[3] * 0.125f + *(float*)(smem + OFF_BIAS + (jg + 1 - ml1 + 31) * 4);
                if (mk0 == 0) { v0 = -1e9f; v2 = -1e9f; }
                if (mk1 == 0) { v1 = -1e9f; v3 = -1e9f; }
                *(float2*)(smem + OFF_SC + ml0 * 4096 + jg * 4) = make_float2(v0, v1);
                *(float2*)(smem + OFF_SC + ml1 * 4096 + jg * 4) = make_float2(v2, v3);
            }
        __syncthreads();
    }

    // ======== softmax over smem rows; write normalized weights ========
    #pragma unroll 1
    for (int rr = 0; rr < 4; rr++) {
        int r = wid * 4 + rr;
        float x[32];
        float mx = -1e30f;
        #pragma unroll
        for (int i = 0; i < 32; i++) {
            x[i] = *(float*)(smem + OFF_SC + r * 4096 + (lane + i * 32) * 4);
            mx = fmaxf(mx, x[i]);
        }
        #pragma unroll
        for (int o = 16; o > 0; o >>= 1)
            mx = fmaxf(mx, __shfl_xor_sync(0xFFFFFFFF, mx, o));
        float s = 0.0f;
        #pragma unroll
        for (int i = 0; i < 32; i++) { x[i] = expf(x[i] - mx); s += x[i]; }
        #pragma unroll
        for (int o = 16; o > 0; o >>= 1)
            s += __shfl_xor_sync(0xFFFFFFFF, s, o);
        float inv = 1.0f / s;
        float* wrow = weights + ((size_t)bh * 1024 + q0 + r) * 1024;
        #pragma unroll
        for (int i = 0; i < 32; i++) {
            float p = x[i] * inv;
            *(float*)(smem + OFF_SC + r * 4096 + (lane + i * 32) * 4) = p;
            wrow[lane + i * 32] = p;
        }
    }
    __syncthreads();

    // ======== AV phase: 16 chunks of 64 s-columns ========
    const int wm2 = wid >> 2, wn2 = wid & 3;
    const int a_row2 = wm2 * 16 + (lane & 15);
    const int b_rowb2 = wn2 * 16 + ((lane >> 4) & 1) * 8 + (lane & 7);
    float cav[2][4];
    #pragma unroll
    for (int j = 0; j < 2; j++)
        #pragma unroll
        for (int u = 0; u < 4; u++) cav[j][u] = 0.0f;

    #pragma unroll 1
    for (int sc2 = 0; sc2 < 16; sc2++) {
        const int s0 = sc2 * 64;
        // fill Vt [d=64][s=64] hi/lo (transpose from V [s][64])
        {
            int s = tid & 63, dblk = tid >> 6;
            const bf16* srcH = QKVH + ((size_t)(2 * BHD + bh) * 1024 + s0 + s) * 64 + dblk * 16;
            const bf16* srcL = QKVL + ((size_t)(2 * BHD + bh) * 1024 + s0 + s) * 64 + dblk * 16;
            union { uint4 v; bf16 e[8]; } h0, h1, l0, l1;
            h0.v = *(const uint4*)srcH; h1.v = *(const uint4*)(srcH + 8);
            l0.v = *(const uint4*)srcL; l1.v = *(const uint4*)(srcL + 8);
            #pragma unroll
            for (int u = 0; u < 8; u++) {
                int d0 = dblk * 16 + u, d1 = dblk * 16 + 8 + u;
                *(bf16*)(smem + OFF_KH + SWZ((uint32_t)(d0 * 128 + s * 2))) = h0.e[u];
                *(bf16*)(smem + OFF_KH + SWZ((uint32_t)(d1 * 128 + s * 2))) = h1.e[u];
                *(bf16*)(smem + OFF_KL + SWZ((uint32_t)(d0 * 128 + s * 2))) = l0.e[u];
                *(bf16*)(smem + OFF_KL + SWZ((uint32_t)(d1 * 128 + s * 2))) = l1.e[u];
            }
        }
        // convert P chunk [32][64] fp32 -> bf16 hi/lo
        {
            int row = tid >> 3, c8 = tid & 7;
            float4 f0 = *(float4*)(smem + OFF_SC + row * 4096 + (s0 + c8 * 8) * 4);
            float4 f1 = *(float4*)(smem + OFF_SC + row * 4096 + (s0 + c8 * 8 + 4) * 4);
            uint32_t sw = SWZ((uint32_t)(row * 128 + c8 * 16));
            uint4 hh = make_uint4(pack_hi(f0.x, f0.y), pack_hi(f0.z, f0.w),
                                  pack_hi(f1.x, f1.y), pack_hi(f1.z, f1.w));
            uint4 ll = make_uint4(pack_lo(f0.x, f0.y), pack_lo(f0.z, f0.w),
                                  pack_lo(f1.x, f1.y), pack_lo(f1.z, f1.w));
            *(uint4*)(smem + OFF_PH + sw) = hh;
            *(uint4*)(smem + OFF_PL + sw) = ll;
        }
        __syncthreads();

        #pragma unroll
        for (int ks = 0; ks < 4; ks++) {
            uint32_t fph[4], fpl[4], fvh[4], fvl[4];
            uint32_t offA = SWZ((uint32_t)(a_row2 * 128 + ks * 32 + a_colb));
            ldsm4(fph, sb + OFF_PH + offA);
            ldsm4(fpl, sb + OFF_PL + offA);
            uint32_t offB = SWZ((uint32_t)(b_rowb2 * 128 + ks * 32 + b_colb));
            ldsm4(fvh, sb + OFF_KH + offB);
            ldsm4(fvl, sb + OFF_KL + offB);
            #pragma unroll
            for (int nt = 0; nt < 2; nt++) {
                hmma(cav[nt], fph, &fvh[nt * 2]);
                hmma(cav[nt], fph, &fvl[nt * 2]);
                hmma(cav[nt], fpl, &fvh[nt * 2]);
            }
        }
        __syncthreads();
    }

    // AO epilogue: bf16 hi/lo [b*1024+s][h*64+d]
    #pragma unroll
    for (int nt = 0; nt < 2; nt++) {
        int s0r = q0 + wm2 * 16 + (lane >> 2);
        int d = wn2 * 16 + nt * 8 + 2 * (lane & 3);
        float* cf = cav[nt];
        size_t i0 = ((size_t)(b * 1024 + s0r)) * 1024 + h * 64 + d;
        size_t i1 = ((size_t)(b * 1024 + s0r + 8)) * 1024 + h * 64 + d;
        *(uint32_t*)(AOH + i0) = pack_hi(cf[0], cf[1]);
        *(uint32_t*)(AOL + i0) = pack_lo(cf[0], cf[1]);
        *(uint32_t*)(AOH + i1) = pack_hi(cf[2], cf[3]);
        *(uint32_t*)(AOL + i1) = pack_lo(cf[2], cf[3]);
    }
}

// ================= launch =================
extern "C" void kernel_launch(void* const* d_in, const int* in_sizes, int n_in,
                              void* d_out, int out_size)
{
    const float* hs   = (const float*)d_in[0];
    const int*   mask = (const int*)  d_in[1];
    const float* Wq   = (const float*)d_in[2];
    const float* Wk   = (const float*)d_in[3];
    const float* Wv   = (const float*)d_in[4];
    const float* Wo   = (const float*)d_in[5];
    const float* rb   = (const float*)d_in[6];
    float* out = (float*)d_out;
    float* weights = out + (size_t)BATCH * S_LEN * DMODEL;

    bf16 *hsH, *hsL, *WH, *WL, *QKVH, *QKVL, *AOH, *AOL;
    cudaGetSymbolAddress((void**)&hsH,  g_hsH);
    cudaGetSymbolAddress((void**)&hsL,  g_hsL);
    cudaGetSymbolAddress((void**)&WH,   g_WH);
    cudaGetSymbolAddress((void**)&WL,   g_WL);
    cudaGetSymbolAddress((void**)&QKVH, g_QKVH);
    cudaGetSymbolAddress((void**)&QKVL, g_QKVL);
    cudaGetSymbolAddress((void**)&AOH,  g_AOH);
    cudaGetSymbolAddress((void**)&AOL,  g_AOL);

    cudaFuncSetAttribute(proj_gemm<0>, cudaFuncAttributeMaxDynamicSharedMemorySize, PSMEM);
    cudaFuncSetAttribute(proj_gemm<1>, cudaFuncAttributeMaxDynamicSharedMemorySize, PSMEM);
    cudaFuncSetAttribute(attn_fused, cudaFuncAttributeMaxDynamicSharedMemorySize, ASMEM);

    // 1. bias table + input splits
    bias_kernel<<<8, 256>>>(rb);
    split_kernel<<<4096, 256>>>(hs, hsH, hsL, 1048576);
    split_kernel<<<1024, 256>>>(Wq, WH,             WL,             262144);
    split_kernel<<<1024, 256>>>(Wk, WH + 1048576,   WL + 1048576,   262144);
    split_kernel<<<1024, 256>>>(Wv, WH + 2097152,   WL + 2097152,   262144);
    split_kernel<<<1024, 256>>>(Wo, WH + 3145728,   WL + 3145728,   262144);

    // 2. Q/K/V projections (z selects weight + dst)
    proj_gemm<1><<<dim3(8, 32, 3), 256, PSMEM>>>(hsH, hsL, WH, WL, nullptr, QKVH, QKVL);

    // 3. fused scores + bias + mask + softmax + weights + AV
    attn_fused<<<dim3(32, 64), 256, ASMEM>>>(mask, weights, QKVH, QKVL, AOH, AOL);

    // 4. output projection
    proj_gemm<0><<<dim3(8, 32, 1), 256, PSMEM>>>(
        AOH, AOL, WH + 3145728, WL + 3145728, out, nullptr, nullptr);
}

// round 5
// speedup vs baseline: 2.4550x; 1.4189x over previous
#include <cuda_runtime.h>
#include <cuda_fp16.h>
#include <math.h>
#include <stdint.h>

#define S_LEN  1024
#define BATCH  4
#define HEADS  16
#define DKV    64
#define DMODEL 1024
#define BHD    (BATCH * HEADS)

// ---------------- scratch (device globals; no allocation allowed) ----------------
__device__ half g_hsH[4096 * 1024];
__device__ half g_hsL[4096 * 1024];
__device__ half g_WH[4 * 1024 * 1024];        // q,k,v,o
__device__ half g_WL[4 * 1024 * 1024];
__device__ half g_QKVH[3 * BHD * 1024 * 64];  // z: 0 Q, 1 K, 2 V; [bh][s][64]
__device__ half g_QKVL[3 * BHD * 1024 * 64];
__device__ half g_AOH[4096 * 1024];
__device__ half g_AOL[4096 * 1024];
__device__ float g_bias2[16 * 2048];          // [h][delta+1023]

// ================= helpers =================
#define SWZ(o) ((o) ^ ((((o) >> 3)) & 0x70))

static __device__ __forceinline__ uint32_t smem_u32(const void* p) {
    uint32_t a;
    asm("{ .reg .u64 t; cvta.to.shared.u64 t, %1; cvt.u32.u64 %0, t; }" : "=r"(a) : "l"(p));
    return a;
}

static __device__ __forceinline__ void ldsm4(uint32_t* r, uint32_t addr) {
    asm volatile("ldmatrix.sync.aligned.m8n8.x4.shared.b16 {%0,%1,%2,%3}, [%4];"
                 : "=r"(r[0]), "=r"(r[1]), "=r"(r[2]), "=r"(r[3]) : "r"(addr));
}
static __device__ __forceinline__ void ldsm4t(uint32_t* r, uint32_t addr) {
    asm volatile("ldmatrix.sync.aligned.m8n8.x4.trans.shared.b16 {%0,%1,%2,%3}, [%4];"
                 : "=r"(r[0]), "=r"(r[1]), "=r"(r[2]), "=r"(r[3]) : "r"(addr));
}

static __device__ __forceinline__ void hmma(float* c, const uint32_t* a, const uint32_t* b) {
    asm volatile(
        "mma.sync.aligned.m16n8k16.row.col.f32.f16.f16.f32 "
        "{%0,%1,%2,%3}, {%4,%5,%6,%7}, {%8,%9}, {%0,%1,%2,%3};"
        : "+f"(c[0]), "+f"(c[1]), "+f"(c[2]), "+f"(c[3])
        : "r"(a[0]), "r"(a[1]), "r"(a[2]), "r"(a[3]), "r"(b[0]), "r"(b[1]));
}

#define CP_ASYNC16(dst, src) \
    asm volatile("cp.async.ca.shared.global [%0], [%1], 16;" :: "r"(dst), "l"(src))
#define CP_COMMIT() asm volatile("cp.async.commit_group;" ::: "memory")
#define CP_WAIT(n)  asm volatile("cp.async.wait_group %0;" :: "n"(n) : "memory")

static __device__ __forceinline__ uint32_t pack_hi(float a, float b) {
    __half2 h = __floats2half2_rn(a, b);
    return *(uint32_t*)&h;
}
static __device__ __forceinline__ uint32_t pack_lo(float a, float b) {
    __half2 h = __floats2half2_rn(a, b);
    float2 f = __half22float2(h);
    __half2 l = __floats2half2_rn(a - f.x, b - f.y);
    return *(uint32_t*)&l;
}

// ================= split fp32 -> fp16 hi/lo =================
__global__ __launch_bounds__(256)
void split_kernel(const float* __restrict__ in, half* __restrict__ hi,
                  half* __restrict__ lo, int n4)
{
    int t = blockIdx.x * blockDim.x + threadIdx.x;
    if (t >= n4) return;
    float4 v = ((const float4*)in)[t];
    uint2 h, l;
    h.x = pack_hi(v.x, v.y); h.y = pack_hi(v.z, v.w);
    l.x = pack_lo(v.x, v.y); l.y = pack_lo(v.z, v.w);
    ((uint2*)hi)[t] = h;
    ((uint2*)lo)[t] = l;
}

// ================= bias table =================
__global__ void bias_kernel(const float* __restrict__ rel_bias) {
    int t = blockIdx.x * blockDim.x + threadIdx.x;
    if (t >= 2048) return;
    int delta = t - 1023;
    int n = -delta;
    int ret = (n < 0) ? 16 : 0;
    n = (n < 0) ? -n : n;
    int bucket;
    if (n < 8) {
        bucket = ret + n;
    } else {
        float x = (logf((float)n * 0.125f) / logf(16.0f)) * 8.0f;
        int v = 8 + (int)x;
        if (v > 15) v = 15;
        bucket = ret + v;
    }
    #pragma unroll
    for (int h = 0; h < HEADS; h++)
        g_bias2[h * 2048 + t] = rel_bias[bucket * HEADS + h];
}

// ================= proj GEMM: C = A * B^T, fp16 split 3-pass ==================
// CTA 128x64, BK=64, 2-stage cp.async, 2 CTAs/SM. 8 warps (4m x 2n), warp 32x32.
// EPI 0: fp32 store C[m][1024]. EPI 1: QKV fp16 hi/lo store, z selects slice.
#define PSTAGE 49152   // A hi 16K | A lo 16K | B hi 8K | B lo 8K
#define PSMEM  (2 * PSTAGE)

template <int EPI>
__global__ __launch_bounds__(256, 2)
void proj_gemm(const half* __restrict__ AH, const half* __restrict__ AL,
               const half* __restrict__ BH, const half* __restrict__ BL,
               float* __restrict__ Cf, half* __restrict__ CH, half* __restrict__ CL)
{
    extern __shared__ char smem[];
    const uint32_t sb = smem_u32(smem);
    const int tid = threadIdx.x;
    const int lane = tid & 31, wid = tid >> 5;
    const int wm = wid >> 1, wn = wid & 1;
    const int m0 = blockIdx.y * 128;
    const int n0 = blockIdx.x * 64;
    const int z = blockIdx.z;

    const half* BHp = BH;
    const half* BLp = BL;
    half* CHp = CH;
    half* CLp = CL;
    if (EPI == 1) {
        BHp += (size_t)z * 1048576; BLp += (size_t)z * 1048576;
        CHp += (size_t)z * 4194304; CLp += (size_t)z * 4194304;
    }

    float c[2][4][4];
    #pragma unroll
    for (int i = 0; i < 2; i++)
        #pragma unroll
        for (int j = 0; j < 4; j++)
            #pragma unroll
            for (int u = 0; u < 4; u++) c[i][j][u] = 0.0f;

    auto fill = [&](int st, int k0) {
        uint32_t base = sb + st * PSTAGE;
        #pragma unroll
        for (int j = 0; j < 4; j++) {
            int idx = j * 256 + tid;
            int row = idx >> 3, seg = idx & 7;
            uint32_t sw = SWZ((uint32_t)(row * 128 + seg * 16));
            CP_ASYNC16(base + sw,         AH + (size_t)(m0 + row) * 1024 + k0 + seg * 8);
            CP_ASYNC16(base + 16384 + sw, AL + (size_t)(m0 + row) * 1024 + k0 + seg * 8);
        }
        #pragma unroll
        for (int j = 0; j < 2; j++) {
            int idx = j * 256 + tid;
            int row = idx >> 3, seg = idx & 7;
            uint32_t sw = SWZ((uint32_t)(row * 128 + seg * 16));
            CP_ASYNC16(base + 32768 + sw, BHp + (size_t)(n0 + row) * 1024 + k0 + seg * 8);
            CP_ASYNC16(base + 40960 + sw, BLp + (size_t)(n0 + row) * 1024 + k0 + seg * 8);
        }
        CP_COMMIT();
    };

    const int a_row = wm * 32 + (lane & 15);
    const int a_cb = (lane >> 4) * 16;
    const int b_row = wn * 32 + ((lane >> 4) & 1) * 8 + (lane & 7);
    const int b_cb = ((lane >> 3) & 1) * 16;

    auto compute = [&](int st) {
        const uint32_t base = sb + st * PSTAGE;
        const uint32_t aH = base, aL = base + 16384;
        const uint32_t bH = base + 32768, bL = base + 40960;
        #pragma unroll
        for (int ks = 0; ks < 4; ks++) {
            uint32_t fah[2][4], fal[2][4], fbh[2][4], fbl[2][4];
            #pragma unroll
            for (int mt = 0; mt < 2; mt++) {
                uint32_t off = SWZ((uint32_t)((a_row + mt * 16) * 128 + ks * 32 + a_cb));
                ldsm4(fah[mt], aH + off);
                ldsm4(fal[mt], aL + off);
            }
            #pragma unroll
            for (int nt2 = 0; nt2 < 2; nt2++) {
                uint32_t off = SWZ((uint32_t)((b_row + nt2 * 16) * 128 + ks * 32 + b_cb));
                ldsm4(fbh[nt2], bH + off);
                ldsm4(fbl[nt2], bL + off);
            }
            #pragma unroll
            for (int mt = 0; mt < 2; mt++)
                #pragma unroll
                for (int nt = 0; nt < 4; nt++) {
                    const uint32_t* ph = &fbh[nt >> 1][(nt & 1) * 2];
                    const uint32_t* pl = &fbl[nt >> 1][(nt & 1) * 2];
                    hmma(c[mt][nt], fah[mt], ph);
                    hmma(c[mt][nt], fah[mt], pl);
                    hmma(c[mt][nt], fal[mt], ph);
                }
        }
    };

    fill(0, 0);
    #pragma unroll 1
    for (int cc = 0; cc < 16; cc++) {
        if (cc + 1 < 16) { fill((cc + 1) & 1, (cc + 1) * 64); CP_WAIT(1); }
        else             { CP_WAIT(0); }
        __syncthreads();
        compute(cc & 1);
        __syncthreads();
    }

    #pragma unroll
    for (int mt = 0; mt < 2; mt++)
        #pragma unroll
        for (int nt = 0; nt < 4; nt++) {
            int mg = m0 + wm * 32 + mt * 16 + (lane >> 2);
            int ng = n0 + wn * 32 + nt * 8 + 2 * (lane & 3);
            float* cf = c[mt][nt];
            if (EPI == 0) {
                *(float2*)(Cf + (size_t)mg * 1024 + ng)       = make_float2(cf[0], cf[1]);
                *(float2*)(Cf + (size_t)(mg + 8) * 1024 + ng) = make_float2(cf[2], cf[3]);
            } else {
                int h = blockIdx.x;
                int d = ng & 63;
                int b = mg >> 10, s = mg & 1023;
                size_t i0 = ((size_t)(b * HEADS + h) * 1024 + s) * 64 + d;
                size_t i1 = i0 + 8 * 64;
                *(uint32_t*)(CHp + i0) = pack_hi(cf[0], cf[1]);
                *(uint32_t*)(CLp + i0) = pack_lo(cf[0], cf[1]);
                *(uint32_t*)(CHp + i1) = pack_hi(cf[2], cf[3]);
                *(uint32_t*)(CLp + i1) = pack_lo(cf[2], cf[3]);
            }
        }
}

// ================= fused attention (16 q-rows per CTA, 2 CTAs/SM) =============
#define OFF_SC   0           // 16x1024 fp32 scores (65536); later: P fp16 [0,32K) + RED [32K,36K)
#define OFF_QH   65536       // Q hi 16x64 (2048)
#define OFF_QL   67584
#define OFF_KH   69632       // K/V chunk 128x64 hi (16384)
#define OFF_KL   86016
#define OFF_BIAS 102400      // 1040 floats (pad 4224)
#define OFF_MASK 106624      // 1024 ints
#define ASMEM    110720
#define OFF_RED  (OFF_SC + 32768)

__global__ __launch_bounds__(256, 2)
void attn_fused(const int* __restrict__ mask, float* __restrict__ weights,
                const half* __restrict__ QKVH, const half* __restrict__ QKVL,
                half* __restrict__ AOH, half* __restrict__ AOL)
{
    extern __shared__ char smem[];
    const uint32_t sb = smem_u32(smem);
    const int tid = threadIdx.x;
    const int lane = tid & 31, wid = tid >> 5;
    const int bh = blockIdx.y;
    const int b = bh >> 4, h = bh & 15;
    const int q0 = blockIdx.x * 16;

    // Q fill + bias + mask
    if (tid < 128) {
        int row = tid >> 3, seg = tid & 7;
        uint32_t sw = SWZ((uint32_t)(row * 128 + seg * 16));
        CP_ASYNC16(sb + OFF_QH + sw, QKVH + ((size_t)bh * 1024 + q0 + row) * 64 + seg * 8);
        CP_ASYNC16(sb + OFF_QL + sw, QKVL + ((size_t)bh * 1024 + q0 + row) * 64 + seg * 8);
    }
    CP_COMMIT();
    for (int i = tid; i < 1040; i += 256)
        *(float*)(smem + OFF_BIAS + i * 4) = g_bias2[h * 2048 + 1008 - q0 + i];
    for (int i = tid; i < 1024; i += 256)
        *(int*)(smem + OFF_MASK + i * 4) = mask[b * 1024 + i];
    CP_WAIT(0);
    __syncthreads();

    // ---- scores: 8 chunks of 128 j ----
    const int wj = wid * 16;
    const int a_row = lane & 15;
    const int a_cb = (lane >> 4) * 16;
    const int b_row = ((lane >> 4) & 1) * 8 + (lane & 7);
    const int b_cb = ((lane >> 3) & 1) * 16;

    #pragma unroll 1
    for (int jc = 0; jc < 8; jc++) {
        const int j0 = jc * 128;
        #pragma unroll
        for (int it = 0; it < 4; it++) {
            int g = it * 256 + tid;
            int row = g >> 3, seg = g & 7;
            uint32_t sw = SWZ((uint32_t)(row * 128 + seg * 16));
            CP_ASYNC16(sb + OFF_KH + sw, QKVH + ((size_t)(BHD + bh) * 1024 + j0 + row) * 64 + seg * 8);
            CP_ASYNC16(sb + OFF_KL + sw, QKVL + ((size_t)(BHD + bh) * 1024 + j0 + row) * 64 + seg * 8);
        }
        CP_COMMIT(); CP_WAIT(0);
        __syncthreads();

        float c2[2][4];
        #pragma unroll
        for (int j = 0; j < 2; j++)
            #pragma unroll
            for (int u = 0; u < 4; u++) c2[j][u] = 0.0f;

        #pragma unroll
        for (int ks = 0; ks < 4; ks++) {
            uint32_t fah[4], fal[4], fbh[4], fbl[4];
            uint32_t offA = SWZ((uint32_t)(a_row * 128 + ks * 32 + a_cb));
            ldsm4(fah, sb + OFF_QH + offA);
            ldsm4(fal, sb + OFF_QL + offA);
            uint32_t offB = SWZ((uint32_t)((wj + b_row) * 128 + ks * 32 + b_cb));
            ldsm4(fbh, sb + OFF_KH + offB);
            ldsm4(fbl, sb + OFF_KL + offB);
            #pragma unroll
            for (int nt = 0; nt < 2; nt++) {
                hmma(c2[nt], fah, &fbh[nt * 2]);
                hmma(c2[nt], fah, &fbl[nt * 2]);
                hmma(c2[nt], fal, &fbh[nt * 2]);
            }
        }

        #pragma unroll
        for (int nt = 0; nt < 2; nt++) {
            int ml0 = lane >> 2, ml1 = ml0 + 8;
            int jg = j0 + wj + nt * 8 + 2 * (lane & 3);
            float* cf = c2[nt];
            int mk0 = *(int*)(smem + OFF_MASK + jg * 4);
            int mk1 = *(int*)(smem + OFF_MASK + (jg + 1) * 4);
            float v0 = cf[0] * 0.125f + *(float*)(smem + OFF_BIAS + (jg - ml0 + 15) * 4);
            float v1 = cf[1] * 0.125f + *(float*)(smem + OFF_BIAS + (jg + 1 - ml0 + 15) * 4);
            float v2 = cf[2] * 0.125f + *(float*)(smem + OFF_BIAS + (jg - ml1 + 15) * 4);
            float v3 = cf[3] * 0.125f + *(float*)(smem + OFF_BIAS + (jg + 1 - ml1 + 15) * 4);
            if (mk0 == 0) { v0 = -1e9f; v2 = -1e9f; }
            if (mk1 == 0) { v1 = -1e9f; v3 = -1e9f; }
            *(float2*)(smem + OFF_SC + ml0 * 4096 + jg * 4) = make_float2(v0, v1);
            *(float2*)(smem + OFF_SC + ml1 * 4096 + jg * 4) = make_float2(v2, v3);
        }
        __syncthreads();
    }

    // ---- softmax: rows 0-7 then 8-15 (warp = row); P stored fp16 swizzled ----
    #pragma unroll 1
    for (int t = 0; t < 2; t++) {
        int r = wid + 8 * t;
        float x[32];
        float mx = -1e30f;
        #pragma unroll
        for (int i = 0; i < 16; i++) {
            float2 f = *(float2*)(smem + OFF_SC + r * 4096 + (2 * lane + 64 * i) * 4);
            x[2 * i] = f.x; x[2 * i + 1] = f.y;
            mx = fmaxf(mx, fmaxf(f.x, f.y));
        }
        #pragma unroll
        for (int o = 16; o > 0; o >>= 1)
            mx = fmaxf(mx, __shfl_xor_sync(0xFFFFFFFF, mx, o));
        float s = 0.0f;
        #pragma unroll
        for (int i = 0; i < 32; i++) { x[i] = expf(x[i] - mx); s += x[i]; }
        #pragma unroll
        for (int o = 16; o > 0; o >>= 1)
            s += __shfl_xor_sync(0xFFFFFFFF, s, o);
        float inv = 1.0f / s;
        __syncthreads();   // all reads of fp32 scores done before fp16 overwrite
        float* wrow = weights + ((size_t)bh * 1024 + q0 + r) * 1024;
        #pragma unroll
        for (int i = 0; i < 16; i++) {
            float p0 = x[2 * i] * inv, p1 = x[2 * i + 1] * inv;
            *(float2*)(wrow + 2 * lane + 64 * i) = make_float2(p0, p1);
            uint32_t jb = (2 * lane + 64 * i) * 2;
            uint32_t addr = OFF_SC + r * 2048 + (((jb >> 4) ^ (r & 7)) << 4) + (jb & 15);
            *(uint32_t*)(smem + addr) = pack_hi(p0, p1);
        }
        __syncthreads();
    }

    // ---- AV: 8 chunks of 128 s; warp = (nt d-slice of 16, kh s-half) ----
    const int nt_w = wid & 3, kh = wid >> 2;
    const int tb_row = (lane & 7) + ((lane >> 3) & 1) * 8;
    const int tb_cb = ((lane >> 4) & 1) * 16;
    float cav[2][4];
    #pragma unroll
    for (int j = 0; j < 2; j++)
        #pragma unroll
        for (int u = 0; u < 4; u++) cav[j][u] = 0.0f;

    #pragma unroll 1
    for (int sc = 0; sc < 8; sc++) {
        const int s0 = sc * 128;
        #pragma unroll
        for (int it = 0; it < 4; it++) {
            int g = it * 256 + tid;
            int row = g >> 3, seg = g & 7;
            uint32_t sw = SWZ((uint32_t)(row * 128 + seg * 16));
            CP_ASYNC16(sb + OFF_KH + sw, QKVH + ((size_t)(2 * BHD + bh) * 1024 + s0 + row) * 64 + seg * 8);
            CP_ASYNC16(sb + OFF_KL + sw, QKVL + ((size_t)(2 * BHD + bh) * 1024 + s0 + row) * 64 + seg * 8);
        }
        CP_COMMIT(); CP_WAIT(0);
        __syncthreads();

        #pragma unroll
        for (int ks = 0; ks < 4; ks++) {
            int kl = kh * 64 + ks * 16;
            uint32_t fp[4], fvh[4], fvl[4];
            uint32_t row = lane & 15;
            uint32_t jb = (uint32_t)(s0 + kl) * 2 + a_cb;
            uint32_t addrA = OFF_SC + row * 2048 + (((jb >> 4) ^ (row & 7)) << 4);
            ldsm4(fp, sb + addrA);
            uint32_t offB = SWZ((uint32_t)((kl + tb_row) * 128 + nt_w * 32 + tb_cb));
            ldsm4t(fvh, sb + OFF_KH + offB);
            ldsm4t(fvl, sb + OFF_KL + offB);
            hmma(cav[0], fp, &fvh[0]);
            hmma(cav[0], fp, &fvl[0]);
            hmma(cav[1], fp, &fvh[2]);
            hmma(cav[1], fp, &fvl[2]);
        }
        __syncthreads();
    }

    // reduce kh=1 into kh=0, then epilogue
    if (kh == 1) {
        #pragma unroll
        for (int f = 0; f < 2; f++)
            *(float4*)(smem + OFF_RED + ((nt_w * 2 + f) * 32 + lane) * 16) =
                make_float4(cav[f][0], cav[f][1], cav[f][2], cav[f][3]);
    }
    __syncthreads();
    if (kh == 0) {
        #pragma unroll
        for (int f = 0; f < 2; f++) {
            float4 r4 = *(float4*)(smem + OFF_RED + ((nt_w * 2 + f) * 32 + lane) * 16);
            cav[f][0] += r4.x; cav[f][1] += r4.y; cav[f][2] += r4.z; cav[f][3] += r4.w;
            int srow = q0 + (lane >> 2);
            int d = nt_w * 16 + f * 8 + 2 * (lane & 3);
            size_t i0 = ((size_t)(b * 1024 + srow)) * 1024 + h * 64 + d;
            size_t i1 = i0 + (size_t)8 * 1024;
            *(uint32_t*)(AOH + i0) = pack_hi(cav[f][0], cav[f][1]);
            *(uint32_t*)(AOL + i0) = pack_lo(cav[f][0], cav[f][1]);
            *(uint32_t*)(AOH + i1) = pack_hi(cav[f][2], cav[f][3]);
            *(uint32_t*)(AOL + i1) = pack_lo(cav[f][2], cav[f][3]);
        }
    }
}

// ================= launch =================
extern "C" void kernel_launch(void* const* d_in, const int* in_sizes, int n_in,
                              void* d_out, int out_size)
{
    const float* hs   = (const float*)d_in[0];
    const int*   mask = (const int*)  d_in[1];
    const float* Wq   = (const float*)d_in[2];
    const float* Wk   = (const float*)d_in[3];
    const float* Wv   = (const float*)d_in[4];
    const float* Wo   = (const float*)d_in[5];
    const float* rb   = (const float*)d_in[6];
    float* out = (float*)d_out;
    float* weights = out + (size_t)BATCH * S_LEN * DMODEL;

    half *hsH, *hsL, *WH, *WL, *QKVH, *QKVL, *AOH, *AOL;
    cudaGetSymbolAddress((void**)&hsH,  g_hsH);
    cudaGetSymbolAddress((void**)&hsL,  g_hsL);
    cudaGetSymbolAddress((void**)&WH,   g_WH);
    cudaGetSymbolAddress((void**)&WL,   g_WL);
    cudaGetSymbolAddress((void**)&QKVH, g_QKVH);
    cudaGetSymbolAddress((void**)&QKVL, g_QKVL);
    cudaGetSymbolAddress((void**)&AOH,  g_AOH);
    cudaGetSymbolAddress((void**)&AOL,  g_AOL);

    cudaFuncSetAttribute(proj_gemm<0>, cudaFuncAttributeMaxDynamicSharedMemorySize, PSMEM);
    cudaFuncSetAttribute(proj_gemm<1>, cudaFuncAttributeMaxDynamicSharedMemorySize, PSMEM);
    cudaFuncSetAttribute(attn_fused, cudaFuncAttributeMaxDynamicSharedMemorySize, ASMEM);

    bias_kernel<<<8, 256>>>(rb);
    split_kernel<<<4096, 256>>>(hs, hsH, hsL, 1048576);
    split_kernel<<<1024, 256>>>(Wq, WH,           WL,           262144);
    split_kernel<<<1024, 256>>>(Wk, WH + 1048576, WL + 1048576, 262144);
    split_kernel<<<1024, 256>>>(Wv, WH + 2097152, WL + 2097152, 262144);
    split_kernel<<<1024, 256>>>(Wo, WH + 3145728, WL + 3145728, 262144);

    // Q/K/V projections (z selects weight + dst slice)
    proj_gemm<1><<<dim3(16, 32, 3), 256, PSMEM>>>(hsH, hsL, WH, WL, nullptr, QKVH, QKVL);

    // fused scores + bias + mask + softmax + weights + AV
    attn_fused<<<dim3(64, 64), 256, ASMEM>>>(mask, weights, QKVH, QKVL, AOH, AOL);

    // output projection
    proj_gemm<0><<<dim3(16, 32, 1), 256, PSMEM>>>(
        AOH, AOL, WH + 3145728, WL + 3145728, out, nullptr, nullptr);
}